// round 5
// baseline (speedup 1.0000x reference)
#include <cuda_runtime.h>
#include <cuda_bf16.h>

// ---------------------------------------------------------------------------
// FocalLoss + ArcFace, B x C (4096 x 32768 f32), targets int (harness lowers
// int64 -> int32), scalar f32 out.
//
// One CTA per row. Stream the row from HBM ONCE (LDG.128), fp32 sum-of-squares
// while staging bf16 into SMEM (64KB -> 3 CTAs/SM, softmax compute overlaps
// other CTAs' HBM loads). Pass 2 sums exp(s*x) from SMEM via ex2.approx
// (|logit| <= 30 so no max-subtraction). Target column fixed up in exact fp32.
// Per-row losses -> __device__ global; tiny deterministic reduce -> mean.
// ---------------------------------------------------------------------------

#define ROW_THREADS 512
#define MAX_B 16384
#define LOG2E 1.4426950408889634f

__device__ float g_rowloss[MAX_B];

__device__ __forceinline__ float fast_ex2(float x) {
    float r;
    asm("ex2.approx.ftz.f32 %0, %1;" : "=f"(r) : "f"(x));
    return r;
}

// Block-wide sum for ROW_THREADS threads. The internal __syncthreads also
// publishes prior SMEM writes by all threads; trailing sync allows `red` reuse.
__device__ __forceinline__ float block_reduce_sum(float v, float* red, int tid) {
    #pragma unroll
    for (int o = 16; o > 0; o >>= 1) v += __shfl_xor_sync(0xffffffffu, v, o);
    const int warp = tid >> 5, lane = tid & 31;
    if (lane == 0) red[warp] = v;
    __syncthreads();
    if (warp == 0) {
        v = (lane < (ROW_THREADS / 32)) ? red[lane] : 0.0f;
        #pragma unroll
        for (int o = 16; o > 0; o >>= 1) v += __shfl_xor_sync(0xffffffffu, v, o);
        if (lane == 0) red[0] = v;
    }
    __syncthreads();
    float r = red[0];
    __syncthreads();
    return r;
}

__global__ __launch_bounds__(ROW_THREADS)
void focal_arcface_row_kernel(const float* __restrict__ x,
                              const int* __restrict__ tgt,
                              int C) {
    extern __shared__ __nv_bfloat16 buf[];   // C bf16 elements (64KB for C=32768)
    __shared__ float red[ROW_THREADS / 32];

    const int row = blockIdx.x;
    const int tid = threadIdx.x;
    const float4* __restrict__ xr =
        reinterpret_cast<const float4*>(x + (size_t)row * (size_t)C);
    uint2* __restrict__ buf2 = reinterpret_cast<uint2*>(buf);
    const int n4 = C >> 2;   // float4 count per row

    // ---- Pass 1: stream row from HBM, fp32 sum-of-squares, stage bf16 ----
    float ss = 0.0f;
    #pragma unroll 4
    for (int j = tid; j < n4; j += ROW_THREADS) {
        float4 v = xr[j];
        ss = fmaf(v.x, v.x, ss);
        ss = fmaf(v.y, v.y, ss);
        ss = fmaf(v.z, v.z, ss);
        ss = fmaf(v.w, v.w, ss);
        __nv_bfloat162 lo = __floats2bfloat162_rn(v.x, v.y);
        __nv_bfloat162 hi = __floats2bfloat162_rn(v.z, v.w);
        uint2 p;
        p.x = *reinterpret_cast<unsigned*>(&lo);
        p.y = *reinterpret_cast<unsigned*>(&hi);
        buf2[j] = p;
    }

    float sumsq = block_reduce_sum(ss, red, tid);
    float norm  = fmaxf(sqrtf(sumsq), 1e-12f);
    float k     = (30.0f / norm) * LOG2E;   // exp(s*x) == exp2(k*x)

    // ---- Pass 2: sum(exp(logit)) over ALL columns (target fixed up later) --
    float se = 0.0f;
    #pragma unroll 4
    for (int j = tid; j < n4; j += ROW_THREADS) {
        uint2 p = ((const uint2*)buf2)[j];
        __nv_bfloat162 lo = *reinterpret_cast<__nv_bfloat162*>(&p.x);
        __nv_bfloat162 hi = *reinterpret_cast<__nv_bfloat162*>(&p.y);
        float2 a = __bfloat1622float2(lo);
        float2 b = __bfloat1622float2(hi);
        se += fast_ex2(a.x * k) + fast_ex2(a.y * k)
            + fast_ex2(b.x * k) + fast_ex2(b.y * k);
    }
    float sum_all = block_reduce_sum(se, red, tid);

    // ---- Per-row scalar epilogue (thread 0) ----
    if (tid == 0) {
        int t = tgt[row];
        t = (t < 0) ? 0 : (t >= C ? C - 1 : t);              // defensive clamp
        float xt   = x[(size_t)row * (size_t)C + (size_t)t]; // exact fp32
        float xt_b = __bfloat162float(buf[t]);               // what pass 2 summed

        // cos(theta) at target, clipped exactly like the reference
        float c = xt / norm;
        c = fminf(fmaxf(c, -1.0f + 1e-7f), 1.0f - 1e-7f);
        // cos(acos(c) + MARGIN) = c*cos(m) - sqrt(1-c^2)*sin(m), exact identity
        const float cosM = 0.95533648912560601964f;  // cos(0.3)
        const float sinM = 0.29552020666133957511f;  // sin(0.3)
        float cosm = c * cosM - sqrtf(fmaxf(1.0f - c * c, 0.0f)) * sinM;
        float lt = 30.0f * cosm;                     // target logit

        // swap target term: remove exp of staged value, add arcface logit exp
        float sum = sum_all - fast_ex2(xt_b * k) + expf(lt);
        float lse = logf(sum);                       // no max needed: |logit|<=30
        float ce  = lse - lt;
        float pt  = expf(-ce);
        float om  = 1.0f - pt;
        g_rowloss[row] = om * om * ce;               // gamma = 2
    }
}

__global__ __launch_bounds__(1024)
void focal_reduce_kernel(int B, float* __restrict__ out) {
    __shared__ float red[32];
    const int tid = threadIdx.x;
    float v = 0.0f;
    for (int i = tid; i < B; i += 1024) v += g_rowloss[i];
    #pragma unroll
    for (int o = 16; o > 0; o >>= 1) v += __shfl_xor_sync(0xffffffffu, v, o);
    const int warp = tid >> 5, lane = tid & 31;
    if (lane == 0) red[warp] = v;
    __syncthreads();
    if (warp == 0) {
        v = red[lane];
        #pragma unroll
        for (int o = 16; o > 0; o >>= 1) v += __shfl_xor_sync(0xffffffffu, v, o);
        if (lane == 0) out[0] = v / (float)B;
    }
}

extern "C" void kernel_launch(void* const* d_in, const int* in_sizes, int n_in,
                              void* d_out, int out_size) {
    // Identify slots by size: the big buffer is `inputs`, the small one `targets`.
    int xi = 0, ti = 1;
    if (n_in >= 2 && in_sizes[1] > in_sizes[0]) { xi = 1; ti = 0; }

    const float* x   = (const float*)d_in[xi];   // inputs  (B*C f32)
    const int*   tgt = (const int*)d_in[ti];     // targets (B, int64 lowered to i32)

    const int B = in_sizes[ti];
    const int C = in_sizes[xi] / B;

    const size_t smem = (size_t)C * sizeof(__nv_bfloat16);  // 64KB for C=32768
    cudaFuncSetAttribute(focal_arcface_row_kernel,
                         cudaFuncAttributeMaxDynamicSharedMemorySize,
                         (int)smem);

    focal_arcface_row_kernel<<<B, ROW_THREADS, smem>>>(x, tgt, C);
    focal_reduce_kernel<<<1, 1024>>>(B, (float*)d_out);
}